// round 4
// baseline (speedup 1.0000x reference)
#include <cuda_runtime.h>

#define BB 128
#define NN 512
#define CC 7
#define HH 64
#define KK 16
#define EPSF 1e-5f

// ---------------- scratch (device globals: allocation-free) ----------------
__device__ float g_hA[BB*NN*HH];      // 16.8 MB
__device__ float g_hB[BB*NN*HH];      // 16.8 MB
__device__ float g_ac[BB*NN*2*HH];    // 33.5 MB  [point][0:64]=a, [64:128]=c
__device__ float g_sq[BB*NN];
__device__ int   g_idx[BB*NN*KK];

// ---------------------------------------------------------------------------
// Kernel A: h = relu(bn2(W2 * relu(bn1(W1 * x))))  per point.
// blockDim (64,16), grid = B*N/16. Thread tx = output channel, ty = point.
// ---------------------------------------------------------------------------
__global__ void k_input(const float* __restrict__ x,
                        const float* __restrict__ w1, const float* __restrict__ g1,
                        const float* __restrict__ b1,
                        const float* __restrict__ w2, const float* __restrict__ g2,
                        const float* __restrict__ b2)
{
    __shared__ float w1s[HH*CC];     // [o*7+c], stride 7 (odd) -> conflict free
    __shared__ float w2sT[HH][HH];   // transposed: [h][o], lanes consecutive o
    __shared__ float xs[16][CC];
    __shared__ float h1s[16][HH];
    int tx = threadIdx.x, ty = threadIdx.y;
    int tid = ty*64 + tx;
    int p0 = blockIdx.x*16;
    int b  = p0 / NN;
    int n0 = p0 % NN;

    for (int i = tid; i < HH*CC; i += 1024) w1s[i] = w1[i];
    for (int i = tid; i < HH*HH; i += 1024) { int o = i>>6, hh = i&63; w2sT[hh][o] = w2[i]; }
    if (tid < 16*CC) { int c = tid/16, i = tid%16; xs[i][c] = x[b*CC*NN + c*NN + n0 + i]; }
    __syncthreads();

    float inv = rsqrtf(1.0f + EPSF);
    float s1 = g1[tx]*inv, bb1 = b1[tx];
    float s2 = g2[tx]*inv, bb2 = b2[tx];

    {   // layer 1: 7 MACs
        float acc = 0.f;
        #pragma unroll
        for (int c = 0; c < CC; c++) acc = fmaf(w1s[tx*CC + c], xs[ty][c], acc);
        h1s[ty][tx] = fmaxf(acc*s1 + bb1, 0.f);
    }
    __syncthreads();
    {   // layer 2: 64 MACs (weight transposed-smem + float4 broadcast h)
        float a0=0,a1=0,a2=0,a3=0;
        const float4* hp = reinterpret_cast<const float4*>(h1s[ty]);
        #pragma unroll
        for (int q = 0; q < 16; q++){
            float4 v = hp[q];
            int hh = q*4;
            a0 = fmaf(w2sT[hh+0][tx], v.x, a0);
            a1 = fmaf(w2sT[hh+1][tx], v.y, a1);
            a2 = fmaf(w2sT[hh+2][tx], v.z, a2);
            a3 = fmaf(w2sT[hh+3][tx], v.w, a3);
        }
        float acc = (a0+a1)+(a2+a3);
        g_hA[(p0+ty)*HH + tx] = fmaxf(acc*s2 + bb2, 0.f);
    }
}

// ---------------------------------------------------------------------------
// squared norms per point. blockDim 256 (8 warps = 8 rows), grid = B*N/8.
// ---------------------------------------------------------------------------
__global__ void k_sq(int src)
{
    const float* h = src ? g_hB : g_hA;
    int w = threadIdx.x >> 5, l = threadIdx.x & 31;
    int row = blockIdx.x*8 + w;
    const float* hp = h + row*HH;
    float v0 = hp[l], v1 = hp[32 + l];
    float s = v0*v0 + v1*v1;
    #pragma unroll
    for (int off = 16; off; off >>= 1) s += __shfl_down_sync(0xffffffffu, s, off);
    if (l == 0) g_sq[row] = s;
}

// ---------------------------------------------------------------------------
// kNN: per thread = one query row (features in regs), stream 64-row m-tiles
// through smem (LDS.128 broadcast). Top-16 kept as sortable u64 keys in smem.
// Key = (monotonic_bits(d) << 32) | m : strict '<' insert + evict-largest-key
// exactly reproduces jax.lax.top_k tie semantics (smaller d, then smaller idx).
// blockDim 128, grid (N/128=4, B=128).
// ---------------------------------------------------------------------------
__global__ __launch_bounds__(128) void k_knn(int src)
{
    const float* h = src ? g_hB : g_hA;
    __shared__ float tile[64*64];                     // 16 KB
    __shared__ unsigned long long kept[KK][128];      // 16 KB
    __shared__ float sqt[64];

    int tid = threadIdx.x;
    int b   = blockIdx.y;
    int n   = blockIdx.x*128 + tid;
    int row = b*NN + n;

    float hn[HH];
    {
        const float4* hp = reinterpret_cast<const float4*>(h + row*HH);
        #pragma unroll
        for (int q = 0; q < 16; q++){
            float4 v = hp[q];
            hn[q*4+0]=v.x; hn[q*4+1]=v.y; hn[q*4+2]=v.z; hn[q*4+3]=v.w;
        }
    }
    float sqn = g_sq[row];

    #pragma unroll
    for (int j = 0; j < KK; j++) kept[j][tid] = ~0ull;
    unsigned long long wkey = ~0ull;
    int ws = 0;

    for (int t = 0; t < 8; t++){
        __syncthreads();
        const float* srcp = h + (b*NN + t*64)*HH;
        for (int i = tid; i < 64*64; i += 128) tile[i] = srcp[i];
        if (tid < 64) sqt[tid] = g_sq[b*NN + t*64 + tid];
        __syncthreads();

        #pragma unroll 1
        for (int mm = 0; mm < 64; mm++){
            const float4* tp = reinterpret_cast<const float4*>(tile + mm*64);
            float a0=0,a1=0,a2=0,a3=0;
            #pragma unroll
            for (int q = 0; q < 16; q++){
                float4 v = tp[q];
                a0 = fmaf(hn[q*4+0], v.x, a0);
                a1 = fmaf(hn[q*4+1], v.y, a1);
                a2 = fmaf(hn[q*4+2], v.z, a2);
                a3 = fmaf(hn[q*4+3], v.w, a3);
            }
            float dot = (a0+a1)+(a2+a3);
            float d = sqn + sqt[mm] - 2.0f*dot;
            unsigned u = __float_as_uint(d);
            u ^= (unsigned)((int)u >> 31) | 0x80000000u;   // monotonic float->uint
            unsigned long long key =
                ((unsigned long long)u << 32) | (unsigned)(t*64 + mm);
            if (key < wkey){
                kept[ws][tid] = key;
                unsigned long long mx = kept[0][tid]; int mslot = 0;
                #pragma unroll
                for (int j = 1; j < KK; j++){
                    unsigned long long kj = kept[j][tid];
                    if (kj > mx){ mx = kj; mslot = j; }
                }
                wkey = mx; ws = mslot;
            }
        }
    }
    #pragma unroll
    for (int j = 0; j < KK; j++)
        g_idx[row*KK + j] = b*NN + (int)(unsigned)(kept[j][tid] & 0xffffffffull);
}

// ---------------------------------------------------------------------------
// a/c GEMM: ac[p][0:64] = s*(W1-W2)h_p + b ;  ac[p][64:128] = s*W2 h_p
// weights in registers (1 row per thread), h broadcast from smem.
// blockDim 128, 32 points/block, grid = B*N/32.
// ---------------------------------------------------------------------------
__global__ __launch_bounds__(128) void k_ac(int src,
    const float* __restrict__ wnb, const float* __restrict__ gnb,
    const float* __restrict__ bnb)
{
    const float* h = src ? g_hB : g_hA;
    __shared__ float hs[32*HH];   // 8 KB
    int t  = threadIdx.x;
    int p0 = blockIdx.x*32;

    float wr[HH]; float bias = 0.f;
    float inv = rsqrtf(1.0f + EPSF);
    if (t < 64){
        float s = gnb[t]*inv;
        bias = bnb[t];
        #pragma unroll
        for (int hh = 0; hh < 64; hh++)
            wr[hh] = (wnb[t*128 + hh] - wnb[t*128 + 64 + hh]) * s;
    } else {
        int o = t - 64;
        float s = gnb[o]*inv;
        #pragma unroll
        for (int hh = 0; hh < 64; hh++)
            wr[hh] = wnb[o*128 + 64 + hh] * s;
    }
    for (int i = t; i < 32*HH; i += 128) hs[i] = h[p0*HH + i];
    __syncthreads();

    #pragma unroll 1
    for (int p = 0; p < 32; p++){
        const float4* hp = reinterpret_cast<const float4*>(hs + p*HH);
        float a0 = bias, a1 = 0, a2 = 0, a3 = 0;
        #pragma unroll
        for (int q = 0; q < 16; q++){
            float4 v = hp[q];
            a0 = fmaf(wr[q*4+0], v.x, a0);
            a1 = fmaf(wr[q*4+1], v.y, a1);
            a2 = fmaf(wr[q*4+2], v.z, a2);
            a3 = fmaf(wr[q*4+3], v.w, a3);
        }
        g_ac[(p0+p)*128 + t] = (a0+a1)+(a2+a3);
    }
}

// ---------------------------------------------------------------------------
// gather-max: h_out[p][ch] = max_k relu(a[p][ch] + c[idx[p][k]][ch])
// blockDim (64,8), grid = B*N/8. dst = the OTHER ping-pong buffer.
// ---------------------------------------------------------------------------
__global__ void k_gmax(int src)
{
    float* out = src ? g_hA : g_hB;
    __shared__ int idxs[8*KK];
    int tx = threadIdx.x, ty = threadIdx.y;
    int tid = ty*64 + tx;
    int p0 = blockIdx.x*8;
    if (tid < 8*KK) idxs[tid] = g_idx[p0*KK + tid];
    __syncthreads();
    int p = p0 + ty;
    float a = g_ac[p*128 + tx];
    float m = 0.f;                       // relu => all candidates >= 0
    #pragma unroll
    for (int k = 0; k < KK; k++){
        int nb = idxs[ty*KK + k];        // already a global row (b*N+m)
        m = fmaxf(m, a + g_ac[nb*128 + 64 + tx]);
    }
    out[p*HH + tx] = m;
}

// ---------------------------------------------------------------------------
// head: u = relu(bn(W_s1 h)); logit = w_s2 . u + b_s2
// blockDim (64,16), grid = B*N/16.
// ---------------------------------------------------------------------------
__global__ void k_head(int src,
    const float* __restrict__ w1, const float* __restrict__ g1,
    const float* __restrict__ b1,
    const float* __restrict__ w2, const float* __restrict__ b2,
    float* __restrict__ out)
{
    const float* h = src ? g_hB : g_hA;
    __shared__ float w1sT[HH][HH];
    __shared__ float hs[16][HH];
    __shared__ float parts[16][2];
    int tx = threadIdx.x, ty = threadIdx.y;
    int tid = ty*64 + tx;
    int p0 = blockIdx.x*16;

    for (int i = tid; i < HH*HH; i += 1024){ int o = i>>6, hh = i&63; w1sT[hh][o] = w1[i]; }
    hs[ty][tx] = h[(p0+ty)*HH + tx];
    __syncthreads();

    float inv = rsqrtf(1.0f + EPSF);
    float s = g1[tx]*inv, bb = b1[tx];
    float a0=0,a1=0,a2=0,a3=0;
    const float4* hp = reinterpret_cast<const float4*>(hs[ty]);
    #pragma unroll
    for (int q = 0; q < 16; q++){
        float4 v = hp[q];
        int hh = q*4;
        a0 = fmaf(w1sT[hh+0][tx], v.x, a0);
        a1 = fmaf(w1sT[hh+1][tx], v.y, a1);
        a2 = fmaf(w1sT[hh+2][tx], v.z, a2);
        a3 = fmaf(w1sT[hh+3][tx], v.w, a3);
    }
    float u = fmaxf(((a0+a1)+(a2+a3))*s + bb, 0.f);
    float v = u * w2[tx];
    #pragma unroll
    for (int off = 16; off; off >>= 1) v += __shfl_down_sync(0xffffffffu, v, off);
    if ((tx & 31) == 0) parts[ty][tx >> 5] = v;
    __syncthreads();
    if (tx == 0) out[p0 + ty] = parts[ty][0] + parts[ty][1] + b2[0];
}

// ---------------------------------------------------------------------------
extern "C" void kernel_launch(void* const* d_in, const int* in_sizes, int n_in,
                              void* d_out, int out_size)
{
    (void)in_sizes; (void)n_in; (void)out_size;
    const float* x    = (const float*)d_in[0];
    const float* w_t1 = (const float*)d_in[1];
    const float* g_t1 = (const float*)d_in[2];
    const float* b_t1 = (const float*)d_in[3];
    const float* w_t2 = (const float*)d_in[4];
    const float* g_t2 = (const float*)d_in[5];
    const float* b_t2 = (const float*)d_in[6];
    const float* w_nb = (const float*)d_in[7];
    const float* g_nb = (const float*)d_in[8];
    const float* b_nb = (const float*)d_in[9];
    const float* w_s1 = (const float*)d_in[10];
    const float* g_s1 = (const float*)d_in[11];
    const float* b_s1 = (const float*)d_in[12];
    const float* w_s2 = (const float*)d_in[13];
    const float* b_s2 = (const float*)d_in[14];
    float* out = (float*)d_out;

    k_input<<<BB*NN/16, dim3(64,16)>>>(x, w_t1, g_t1, b_t1, w_t2, g_t2, b_t2);

    for (int r = 0; r < 2; r++){
        // r==0: read g_hA, write g_hB ; r==1: read g_hB, write g_hA
        k_sq  <<<BB*NN/8, 256>>>(r);
        k_knn <<<dim3(4,128), 128>>>(r);
        k_ac  <<<BB*NN/32, 128>>>(r, w_nb + r*64*128, g_nb + r*64, b_nb + r*64);
        k_gmax<<<BB*NN/8, dim3(64,8)>>>(r);
    }

    // after two rounds, current features live in g_hA (src flag 0)
    k_head<<<BB*NN/16, dim3(64,16)>>>(0, w_s1, g_s1, b_s1, w_s2, b_s2, out);
}

// round 5
// speedup vs baseline: 1.2138x; 1.2138x over previous
#include <cuda_runtime.h>

#define BB 128
#define NN 512
#define CC 7
#define HH 64
#define KK 16
#define EPSF 1e-5f

typedef unsigned long long ull;

// ---------------- scratch (device globals: allocation-free) ----------------
__device__ __align__(16) float g_hA[BB*NN*HH];      // 16.8 MB
__device__ __align__(16) float g_hB[BB*NN*HH];      // 16.8 MB
__device__ __align__(16) float g_ac[BB*NN*2*HH];    // 33.5 MB  [point][0:64]=a, [64:128]=c
__device__ float g_sq[BB*NN];
__device__ int   g_idx[BB*NN*KK];
__device__ float g_wfT[2*HH*128];                   // folded weights, [r][hh][o] (transposed)
__device__ float g_wb[2*HH];                        // folded bias

// ---------------- packed fp32x2 helpers (Blackwell f32x2 pipe) -------------
__device__ __forceinline__ ull fma2(ull a, ull b, ull c){
    ull d; asm("fma.rn.f32x2 %0, %1, %2, %3;" : "=l"(d) : "l"(a), "l"(b), "l"(c)); return d;
}
__device__ __forceinline__ ull add2(ull a, ull b){
    ull d; asm("add.rn.f32x2 %0, %1, %2;" : "=l"(d) : "l"(a), "l"(b)); return d;
}
__device__ __forceinline__ float lo2(ull a){ return __uint_as_float((unsigned)a); }
__device__ __forceinline__ float hi2(ull a){ return __uint_as_float((unsigned)(a >> 32)); }
__device__ __forceinline__ ull pk2(float lo, float hi){
    ull d; asm("mov.b64 %0, {%1,%2};" : "=l"(d) : "f"(lo), "f"(hi)); return d;
}

// ---------------------------------------------------------------------------
// k_prep: fold BN scale into edgeconv weights, TRANSPOSED layout [r][hh][o]
// so k_ac's per-thread weight loads are coalesced. Runs every replay.
// ---------------------------------------------------------------------------
__global__ void k_prep(const float* __restrict__ wnb,
                       const float* __restrict__ gnb,
                       const float* __restrict__ bnb)
{
    int i = blockIdx.x*256 + threadIdx.x;
    if (i < 2*HH) g_wb[i] = bnb[i];
    if (i >= 2*HH*128) return;
    int r   = i >> 13;          // 8192 entries per round
    int rem = i & 8191;
    int hh  = rem >> 7;         // input channel 0..63
    int o   = rem & 127;        // output row 0..127 (0:63 = a-weights, 64:127 = c-weights)
    float inv = rsqrtf(1.0f + EPSF);
    float v;
    if (o < HH){
        float s = gnb[r*HH + o] * inv;
        v = (wnb[(r*HH + o)*128 + hh] - wnb[(r*HH + o)*128 + 64 + hh]) * s;
    } else {
        int oo = o - HH;
        float s = gnb[r*HH + oo] * inv;
        v = wnb[(r*HH + oo)*128 + 64 + hh] * s;
    }
    g_wfT[i] = v;
}

// ---------------------------------------------------------------------------
// k_input: h = relu(bn2(W2 relu(bn1(W1 x)))), fused row-norm (g_sq).
// blockDim (64,16), grid = B*N/16.
// ---------------------------------------------------------------------------
__global__ void k_input(const float* __restrict__ x,
                        const float* __restrict__ w1, const float* __restrict__ g1,
                        const float* __restrict__ b1,
                        const float* __restrict__ w2, const float* __restrict__ g2,
                        const float* __restrict__ b2)
{
    __shared__ float w1s[HH*CC];
    __shared__ float w2sT[HH][HH];
    __shared__ float xs[16][CC];
    __shared__ __align__(16) float h1s[16][HH];
    __shared__ float part[32];
    int tx = threadIdx.x, ty = threadIdx.y;
    int tid = ty*64 + tx;
    int p0 = blockIdx.x*16;
    int b  = p0 / NN;
    int n0 = p0 % NN;

    for (int i = tid; i < HH*CC; i += 1024) w1s[i] = w1[i];
    for (int i = tid; i < HH*HH; i += 1024) { int o = i>>6, hh = i&63; w2sT[hh][o] = w2[i]; }
    if (tid < 16*CC) { int c = tid/16, i = tid%16; xs[i][c] = x[b*CC*NN + c*NN + n0 + i]; }
    __syncthreads();

    float inv = rsqrtf(1.0f + EPSF);
    float s1 = g1[tx]*inv, bb1 = b1[tx];
    float s2 = g2[tx]*inv, bb2 = b2[tx];

    {
        float acc = 0.f;
        #pragma unroll
        for (int c = 0; c < CC; c++) acc = fmaf(w1s[tx*CC + c], xs[ty][c], acc);
        h1s[ty][tx] = fmaxf(acc*s1 + bb1, 0.f);
    }
    __syncthreads();
    float val;
    {
        float a0=0,a1=0,a2=0,a3=0;
        const float4* hp = reinterpret_cast<const float4*>(h1s[ty]);
        #pragma unroll
        for (int q = 0; q < 16; q++){
            float4 v = hp[q];
            int hh = q*4;
            a0 = fmaf(w2sT[hh+0][tx], v.x, a0);
            a1 = fmaf(w2sT[hh+1][tx], v.y, a1);
            a2 = fmaf(w2sT[hh+2][tx], v.z, a2);
            a3 = fmaf(w2sT[hh+3][tx], v.w, a3);
        }
        val = fmaxf(((a0+a1)+(a2+a3))*s2 + bb2, 0.f);
        g_hA[(p0+ty)*HH + tx] = val;
    }
    // fused squared norm: two warps per row
    float ss = val*val;
    #pragma unroll
    for (int off = 16; off; off >>= 1) ss += __shfl_down_sync(0xffffffffu, ss, off);
    if ((tx & 31) == 0) part[tid >> 5] = ss;
    __syncthreads();
    if (tx == 0) g_sq[p0 + ty] = part[2*ty] + part[2*ty + 1];
}

// ---------------------------------------------------------------------------
// kNN: thread = one query row (features packed in 32 u64 regs, f32x2 FMA).
// 64 queries/block, grid (8, 128) = 1024 blocks. Top-16 via sortable u64 keys
// (evict-max scan) -> exact jax.lax.top_k tie semantics.
// ---------------------------------------------------------------------------
__global__ __launch_bounds__(64) void k_knn(int src)
{
    const float* h = src ? g_hB : g_hA;
    __shared__ __align__(16) float tile[64*64];   // 16 KB
    __shared__ ull kept[KK][64];                  // 8 KB
    __shared__ float sqt[64];

    int tid = threadIdx.x;
    int b   = blockIdx.y;
    int n   = blockIdx.x*64 + tid;
    int row = b*NN + n;

    ull hq[32];
    {
        const longlong2* hp = reinterpret_cast<const longlong2*>(h + row*HH);
        #pragma unroll
        for (int q = 0; q < 16; q++){
            longlong2 v = hp[q];
            hq[2*q]   = (ull)v.x;
            hq[2*q+1] = (ull)v.y;
        }
    }
    float sqn = g_sq[row];

    #pragma unroll
    for (int j = 0; j < KK; j++) kept[j][tid] = ~0ull;
    ull wkey = ~0ull;
    int ws = 0;

    for (int t = 0; t < 8; t++){
        __syncthreads();
        const float4* s4 = reinterpret_cast<const float4*>(h + (b*NN + t*64)*HH);
        float4* t4 = reinterpret_cast<float4*>(tile);
        #pragma unroll
        for (int i = 0; i < 16; i++) t4[tid + i*64] = s4[tid + i*64];
        sqt[tid] = g_sq[b*NN + t*64 + tid];
        __syncthreads();

        #pragma unroll 1
        for (int mm = 0; mm < 64; mm++){
            const longlong2* tp = reinterpret_cast<const longlong2*>(tile + mm*64);
            ull a0=0, a1=0, a2=0, a3=0;
            #pragma unroll
            for (int q = 0; q < 8; q++){
                longlong2 v = tp[q];
                a0 = fma2(hq[2*q],   (ull)v.x, a0);
                a1 = fma2(hq[2*q+1], (ull)v.y, a1);
            }
            #pragma unroll
            for (int q = 8; q < 16; q++){
                longlong2 v = tp[q];
                a2 = fma2(hq[2*q],   (ull)v.x, a2);
                a3 = fma2(hq[2*q+1], (ull)v.y, a3);
            }
            ull sv = add2(add2(a0,a2), add2(a1,a3));
            float dot = lo2(sv) + hi2(sv);
            float d = sqn + sqt[mm] - 2.0f*dot;
            unsigned u = __float_as_uint(d);
            u ^= (unsigned)((int)u >> 31) | 0x80000000u;   // monotonic float->uint
            ull key = ((ull)u << 32) | (unsigned)(t*64 + mm);
            if (key < wkey){
                kept[ws][tid] = key;
                ull mx = kept[0][tid]; int ms = 0;
                #pragma unroll
                for (int j = 1; j < KK; j++){
                    ull kj = kept[j][tid];
                    if (kj > mx){ mx = kj; ms = j; }
                }
                wkey = mx; ws = ms;
            }
        }
    }
    #pragma unroll
    for (int j = 0; j < KK; j++)
        g_idx[row*KK + j] = b*NN + (int)(unsigned)(kept[j][tid] & 0xffffffffull);
}

// ---------------------------------------------------------------------------
// a/c GEMM: ac[p][0:64] = (folded A-weights)h_p + b ; ac[p][64:128] = Cw h_p
// Weights from transposed, pre-folded g_wfT (coalesced, L1-resident).
// blockDim 128, 64 points/block, grid = B*N/64. f32x2 FMA.
// ---------------------------------------------------------------------------
__global__ __launch_bounds__(128) void k_ac(int r, int src)
{
    const float* h = src ? g_hB : g_hA;
    __shared__ __align__(16) float hs[64*HH];   // 16 KB
    int t  = threadIdx.x;
    int p0 = blockIdx.x*64;

    ull wq[32];
    const float* wbase = g_wfT + r*8192;
    #pragma unroll
    for (int j = 0; j < 32; j++){
        float wa = wbase[(2*j  )*128 + t];
        float wb = wbase[(2*j+1)*128 + t];
        wq[j] = pk2(wa, wb);
    }
    float bias = (t < HH) ? g_wb[r*HH + t] : 0.f;

    const float4* src4 = reinterpret_cast<const float4*>(h + p0*HH);
    float4* hs4 = reinterpret_cast<float4*>(hs);
    for (int i = t; i < 1024; i += 128) hs4[i] = src4[i];
    __syncthreads();

    #pragma unroll 2
    for (int p = 0; p < 64; p++){
        const longlong2* hp = reinterpret_cast<const longlong2*>(hs + p*HH);
        ull a0=0, a1=0, a2=0, a3=0;
        #pragma unroll
        for (int q = 0; q < 8; q++){
            longlong2 v = hp[q];
            a0 = fma2(wq[2*q],   (ull)v.x, a0);
            a1 = fma2(wq[2*q+1], (ull)v.y, a1);
        }
        #pragma unroll
        for (int q = 8; q < 16; q++){
            longlong2 v = hp[q];
            a2 = fma2(wq[2*q],   (ull)v.x, a2);
            a3 = fma2(wq[2*q+1], (ull)v.y, a3);
        }
        ull sv = add2(add2(a0,a2), add2(a1,a3));
        g_ac[(p0+p)*128 + t] = bias + lo2(sv) + hi2(sv);
    }
}

// ---------------------------------------------------------------------------
// gather-max + fused row-norm of the output (feeds next round's kNN).
// h_out[p][ch] = max_k relu(a[p][ch] + c[idx[p][k]][ch])
// blockDim (64,8), grid = B*N/8.
// ---------------------------------------------------------------------------
__global__ void k_gmax(int src)
{
    float* out = src ? g_hA : g_hB;
    __shared__ int idxs[8*KK];
    __shared__ float part[16];
    int tx = threadIdx.x, ty = threadIdx.y;
    int tid = ty*64 + tx;
    int p0 = blockIdx.x*8;
    if (tid < 8*KK) idxs[tid] = g_idx[p0*KK + tid];
    __syncthreads();
    int p = p0 + ty;
    float a = g_ac[p*128 + tx];
    float m = 0.f;                        // relu => candidates clamped at 0
    #pragma unroll
    for (int k = 0; k < KK; k++){
        int nb = idxs[ty*KK + k];
        m = fmaxf(m, a + g_ac[nb*128 + 64 + tx]);
    }
    out[p*HH + tx] = m;

    float ss = m*m;
    #pragma unroll
    for (int off = 16; off; off >>= 1) ss += __shfl_down_sync(0xffffffffu, ss, off);
    if ((tx & 31) == 0) part[tid >> 5] = ss;
    __syncthreads();
    if (tx == 0) g_sq[p] = part[2*ty] + part[2*ty + 1];
}

// ---------------------------------------------------------------------------
// head: u = relu(bn(W_s1 h)); logit = w_s2 . u + b_s2
// blockDim (64,16), grid = B*N/16.
// ---------------------------------------------------------------------------
__global__ void k_head(int src,
    const float* __restrict__ w1, const float* __restrict__ g1,
    const float* __restrict__ b1,
    const float* __restrict__ w2, const float* __restrict__ b2,
    float* __restrict__ out)
{
    const float* h = src ? g_hB : g_hA;
    __shared__ float w1sT[HH][HH];
    __shared__ __align__(16) float hs[16][HH];
    __shared__ float parts[16][2];
    int tx = threadIdx.x, ty = threadIdx.y;
    int tid = ty*64 + tx;
    int p0 = blockIdx.x*16;

    for (int i = tid; i < HH*HH; i += 1024){ int o = i>>6, hh = i&63; w1sT[hh][o] = w1[i]; }
    hs[ty][tx] = h[(p0+ty)*HH + tx];
    __syncthreads();

    float inv = rsqrtf(1.0f + EPSF);
    float s = g1[tx]*inv, bb = b1[tx];
    float a0=0,a1=0,a2=0,a3=0;
    const float4* hp = reinterpret_cast<const float4*>(hs[ty]);
    #pragma unroll
    for (int q = 0; q < 16; q++){
        float4 v = hp[q];
        int hh = q*4;
        a0 = fmaf(w1sT[hh+0][tx], v.x, a0);
        a1 = fmaf(w1sT[hh+1][tx], v.y, a1);
        a2 = fmaf(w1sT[hh+2][tx], v.z, a2);
        a3 = fmaf(w1sT[hh+3][tx], v.w, a3);
    }
    float u = fmaxf(((a0+a1)+(a2+a3))*s + bb, 0.f);
    float v = u * w2[tx];
    #pragma unroll
    for (int off = 16; off; off >>= 1) v += __shfl_down_sync(0xffffffffu, v, off);
    if ((tx & 31) == 0) parts[ty][tx >> 5] = v;
    __syncthreads();
    if (tx == 0) out[p0 + ty] = parts[ty][0] + parts[ty][1] + b2[0];
}

// ---------------------------------------------------------------------------
extern "C" void kernel_launch(void* const* d_in, const int* in_sizes, int n_in,
                              void* d_out, int out_size)
{
    (void)in_sizes; (void)n_in; (void)out_size;
    const float* x    = (const float*)d_in[0];
    const float* w_t1 = (const float*)d_in[1];
    const float* g_t1 = (const float*)d_in[2];
    const float* b_t1 = (const float*)d_in[3];
    const float* w_t2 = (const float*)d_in[4];
    const float* g_t2 = (const float*)d_in[5];
    const float* b_t2 = (const float*)d_in[6];
    const float* w_nb = (const float*)d_in[7];
    const float* g_nb = (const float*)d_in[8];
    const float* b_nb = (const float*)d_in[9];
    const float* w_s1 = (const float*)d_in[10];
    const float* g_s1 = (const float*)d_in[11];
    const float* b_s1 = (const float*)d_in[12];
    const float* w_s2 = (const float*)d_in[13];
    const float* b_s2 = (const float*)d_in[14];
    float* out = (float*)d_out;

    k_prep<<<64, 256>>>(w_nb, g_nb, b_nb);
    k_input<<<BB*NN/16, dim3(64,16)>>>(x, w_t1, g_t1, b_t1, w_t2, g_t2, b_t2);

    for (int r = 0; r < 2; r++){
        // r==0: read g_hA, write g_hB ; r==1: read g_hB, write g_hA
        k_knn <<<dim3(8,128), 64>>>(r);
        k_ac  <<<BB*NN/64, 128>>>(r, r);
        k_gmax<<<BB*NN/8, dim3(64,8)>>>(r);
    }

    k_head<<<BB*NN/16, dim3(64,16)>>>(0, w_s1, g_s1, b_s1, w_s2, b_s2, out);
}